// round 10
// baseline (speedup 1.0000x reference)
#include <cuda_runtime.h>
#include <math.h>
#include <stdint.h>

// Problem constants
#define S_LEN 2048
#define EDIM  1024
#define NH    8
#define DH    128
#define BM    64
#define BN    64

typedef unsigned long long ull;

// ---- packed f32x2 helpers (Blackwell FFMA2 — PTX-only path) ----
__device__ __forceinline__ ull ffma2(ull a, ull b, ull c) {
    ull d;
    asm("fma.rn.f32x2 %0, %1, %2, %3;" : "=l"(d) : "l"(a), "l"(b), "l"(c));
    return d;
}
__device__ __forceinline__ ull fmul2(ull a, ull b) {
    ull d;
    asm("mul.rn.f32x2 %0, %1, %2;" : "=l"(d) : "l"(a), "l"(b));
    return d;
}
__device__ __forceinline__ ull dup2f(float x) {
    ull d;
    asm("mov.b64 %0, {%1, %1};" : "=l"(d) : "f"(x));
    return d;
}
__device__ __forceinline__ void unpk2(ull v, float& lo, float& hi) {
    asm("mov.b64 {%0, %1}, %2;" : "=f"(lo), "=f"(hi) : "l"(v));
}
__device__ __forceinline__ void cp16(uint32_t dst, const float* src) {
    asm volatile("cp.async.cg.shared.global [%0], [%1], 16;" :: "r"(dst), "l"(src));
}
__device__ __forceinline__ void cp_commit() {
    asm volatile("cp.async.commit_group;");
}
__device__ __forceinline__ void cp_wait0() {
    asm volatile("cp.async.wait_group 0;");
}
__device__ __forceinline__ void cp_wait1() {
    asm volatile("cp.async.wait_group 1;");
}

// Scratch (device globals: no allocations allowed)
__device__ float g_ig  [NH * S_LEN];
__device__ float g_logf[NH * S_LEN];
__device__ float g_cumS[NH * S_LEN];    // inclusive scan
__device__ float g_h   [S_LEN * EDIM];

// ---------------------------------------------------------------------------
// Kernel 1: gate projections.
// ---------------------------------------------------------------------------
__global__ void gates_kernel(const float* __restrict__ q,
                             const float* __restrict__ k,
                             const float* __restrict__ v,
                             const float* __restrict__ Wi,
                             const float* __restrict__ bi,
                             const float* __restrict__ Wf,
                             const float* __restrict__ bf) {
    const int b = blockIdx.x;
    const int tid = threadIdx.x;

    float acc[64];
#pragma unroll
    for (int i = 0; i < 64; i++) acc[i] = 0.f;

#pragma unroll 1
    for (int it = 0; it < 12; it++) {
        const int j = it * 256 + tid;
        float wi[8], wf[8];
#pragma unroll
        for (int h = 0; h < 8; h++) {
            wi[h] = Wi[h * 3072 + j];
            wf[h] = Wf[h * 3072 + j];
        }
#pragma unroll
        for (int r = 0; r < 4; r++) {
            const int s = b * 4 + r;
            float x;
            if (j < 1024)       x = q[s * 1024 + j];
            else if (j < 2048)  x = k[s * 1024 + (j - 1024)];
            else                x = v[s * 1024 + (j - 2048)];
#pragma unroll
            for (int h = 0; h < 8; h++) {
                acc[r * 16 + h]     = fmaf(x, wi[h], acc[r * 16 + h]);
                acc[r * 16 + 8 + h] = fmaf(x, wf[h], acc[r * 16 + 8 + h]);
            }
        }
    }

#pragma unroll
    for (int i = 0; i < 64; i++) {
#pragma unroll
        for (int off = 16; off > 0; off >>= 1)
            acc[i] += __shfl_xor_sync(0xffffffffu, acc[i], off);
    }
    __shared__ float red[8][64];
    const int warp = tid >> 5, lane = tid & 31;
    if (lane == 0) {
#pragma unroll
        for (int i = 0; i < 64; i++) red[warp][i] = acc[i];
    }
    __syncthreads();
    if (tid < 64) {
        float vsum = 0.f;
#pragma unroll
        for (int w = 0; w < 8; w++) vsum += red[w][tid];
        const int r = tid >> 4;
        const int o = tid & 15;
        const int h = o & 7;
        const int s = b * 4 + r;
        if (o < 8) {
            g_ig[h * S_LEN + s] = vsum + bi[h];
        } else {
            const float fg = vsum + bf[h];
            g_logf[h * S_LEN + s] = fminf(fg, 0.f) - log1pf(expf(-fabsf(fg)));
        }
    }
}

// ---------------------------------------------------------------------------
// Kernel 2: per-head inclusive scan of log_f (double precision).
// ---------------------------------------------------------------------------
__global__ void scan_kernel() {
    const int h = blockIdx.x;
    const int tid = threadIdx.x;
    const int lane = tid & 31, warp = tid >> 5;

    const double x0 = (double)g_logf[h * S_LEN + 2 * tid];
    const double x1 = (double)g_logf[h * S_LEN + 2 * tid + 1];
    const double s = x0 + x1;

    double inc = s;
#pragma unroll
    for (int off = 1; off < 32; off <<= 1) {
        double u = __shfl_up_sync(0xffffffffu, inc, off);
        if (lane >= off) inc += u;
    }
    __shared__ double wsum[32];
    if (lane == 31) wsum[warp] = inc;
    __syncthreads();
    if (warp == 0) {
        double w = wsum[lane];
#pragma unroll
        for (int off = 1; off < 32; off <<= 1) {
            double u = __shfl_up_sync(0xffffffffu, w, off);
            if (lane >= off) w += u;
        }
        wsum[lane] = w;
    }
    __syncthreads();
    const double base = (warp > 0) ? wsum[warp - 1] : 0.0;
    const double incl = base + inc;
    const double excl = incl - s;

    float* cum = g_cumS + h * S_LEN;
    cum[2 * tid]     = (float)(excl + x0);
    cum[2 * tid + 1] = (float)incl;
}

// ---------------------------------------------------------------------------
// Kernel 3: main flash-style mLSTM attention. Single-buffered, split K/V
// pipeline, Q/K/V all cp.async + swizzled, 2 CTAs/SM.
// grid 256 = (32 qtiles x 8 heads), 256 threads, 4x4 micro-tiles.
// ---------------------------------------------------------------------------
#define QS_OFF 0
#define KS_OFF (64 * 128)                  // Q: 8192 floats (swizzled)
#define VS_OFF (KS_OFF + 64 * 128)         // K: 8192 (swizzled)
#define PS_OFF (VS_OFF + 64 * 128)         // V: 8192
#define SMEM_FLOATS (PS_OFF + 64 * 68)     // P: 4352  -> 28928 fl = 115712 B
#define SMEM_BYTES (SMEM_FLOATS * 4)

// swizzled [64][128] tile: row r, 4-float chunk ch at (r*128 + ((ch^swz(r))<<2))
__device__ __forceinline__ void prefetch_swz(const float* __restrict__ g,
                                             float* sb, int tid) {
    uint32_t base = (uint32_t)__cvta_generic_to_shared(sb);
#pragma unroll
    for (int it = 0; it < 8; it++) {
        const int c = it * 256 + tid;     // 0..2047 chunks of 16B
        const int row = c >> 5, ch = c & 31;
        const int swz = (row ^ (row >> 3)) & 7;
        cp16(base + (uint32_t)(row * 128 + ((ch ^ swz) << 2)) * 4u,
             g + row * EDIM + ch * 4);
    }
    cp_commit();
}
__device__ __forceinline__ void prefetch_V(const float* __restrict__ vg,
                                           float* Vsb, int tid) {
    uint32_t vbase = (uint32_t)__cvta_generic_to_shared(Vsb);
#pragma unroll
    for (int it = 0; it < 8; it++) {
        const int c = it * 256 + tid;
        const int key = c >> 5, ch = c & 31;
        cp16(vbase + (uint32_t)(key * 128 + (ch << 2)) * 4u,
             vg + key * EDIM + ch * 4);
    }
    cp_commit();
}

extern "C" __global__ void __launch_bounds__(256, 2)
mlstm_main_kernel(const float* __restrict__ q,
                  const float* __restrict__ k,
                  const float* __restrict__ v) {
    extern __shared__ float sm[];
    float* Qs = sm + QS_OFF;    // [64][128] swizzled
    float* Ks = sm + KS_OFF;    // [64][128] swizzled
    float* Vs = sm + VS_OFF;    // [64][128]
    float* Ps = sm + PS_OFF;    // [64][68]  Ps[key][row]

    const int bx = blockIdx.x;
    const int qi = 31 - (bx >> 3);       // longest-work-first
    const int h  = bx & 7;
    const int tid = threadIdx.x;
    const int tx = tid & 15;             // 16 col-groups (keys)
    const int ty = tid >> 4;             // 16 row-groups (queries)

    const float scale = 0.08838834764831845f;  // 1/sqrt(128)
    const float* kg0 = k + h * DH;
    const float* vg0 = v + h * DH;
    const int qrow0 = qi * BM;

    // prefetch: K(0), Q, V(0) — three commit groups
    prefetch_swz(kg0, Ks, tid);
    prefetch_swz(q + (size_t)qrow0 * EDIM + h * DH, Qs, tid);
    prefetch_V(vg0, Vs, tid);

    float cumq[4];
    int srow[4];
#pragma unroll
    for (int i = 0; i < 4; i++) {
        srow[i] = qrow0 + ty * 4 + i;
        cumq[i] = g_cumS[h * S_LEN + srow[i]];
    }

    int kswz[4], qswz[4];
#pragma unroll
    for (int j = 0; j < 4; j++) {
        const int rk = 4 * tx + j;
        kswz[j] = (rk ^ (rk >> 3)) & 7;
        const int rq = 4 * ty + j;
        qswz[j] = (rq ^ (rq >> 3)) & 7;
    }

    float m[4], l[4];
    ull o2[4][4];
#pragma unroll
    for (int i = 0; i < 4; i++) {
        m[i] = -INFINITY; l[i] = 0.f;
#pragma unroll
        for (int d = 0; d < 4; d++) o2[i][d] = 0ull;
    }

    cp_wait1();        // K(0) + Q done (all but newest group = V(0))
    __syncthreads();

    for (int kt = 0; kt <= qi; kt++) {
        const int t0 = kt * BN;

        // gate inputs for this thread's 4 keys
        const int c0 = tx * 4;
        const float4 igv  = *(const float4*)(g_ig   + h * S_LEN + t0 + c0);
        const float4 cumv = *(const float4*)(g_cumS + h * S_LEN + t0 + c0);
        float Bc[4] = {igv.x - cumv.x, igv.y - cumv.y,
                       igv.z - cumv.z, igv.w - cumv.w};

        // ---- QK^T 64x64x128, dot along k, packed pairs ----
        ull acc2[4][4];
#pragma unroll
        for (int i = 0; i < 4; i++)
#pragma unroll
            for (int j = 0; j < 4; j++) acc2[i][j] = 0ull;

#pragma unroll 8
        for (int ch = 0; ch < 32; ch++) {
            ulonglong2 qv[4], kv[4];
#pragma unroll
            for (int i = 0; i < 4; i++)
                qv[i] = *(const ulonglong2*)(Qs + (4 * ty + i) * 128 + ((ch ^ qswz[i]) << 2));
#pragma unroll
            for (int j = 0; j < 4; j++)
                kv[j] = *(const ulonglong2*)(Ks + (4 * tx + j) * 128 + ((ch ^ kswz[j]) << 2));
#pragma unroll
            for (int i = 0; i < 4; i++)
#pragma unroll
                for (int j = 0; j < 4; j++) {
                    acc2[i][j] = ffma2(qv[i].x, kv[j].x, acc2[i][j]);
                    acc2[i][j] = ffma2(qv[i].y, kv[j].y, acc2[i][j]);
                }
        }
        float acc[4][4];
#pragma unroll
        for (int i = 0; i < 4; i++)
#pragma unroll
            for (int j = 0; j < 4; j++) {
                float lo, hi; unpk2(acc2[i][j], lo, hi);
                acc[i][j] = lo + hi;
            }

        // ---- gate math (scale folded into the exp coefficient) ----
        float P[4][4], fs[4], tl[4];
        if (kt < qi) {
            float bmax = fmaxf(fmaxf(Bc[0], Bc[1]), fmaxf(Bc[2], Bc[3]));
#pragma unroll
            for (int off = 1; off < 16; off <<= 1)
                bmax = fmaxf(bmax, __shfl_xor_sync(0xffffffffu, bmax, off, 16));
            float eB[4];
#pragma unroll
            for (int j = 0; j < 4; j++) eB[j] = __expf(Bc[j] - bmax);
#pragma unroll
            for (int i = 0; i < 4; i++) {
                const float mn = fmaxf(m[i], cumq[i] + bmax);
                fs[i] = __expf(m[i] - mn);
                m[i] = mn;
                const float eA = scale * __expf(cumq[i] - mn + bmax);
                float rs = 0.f;
#pragma unroll
                for (int j = 0; j < 4; j++) {
                    const float p = acc[i][j] * eA * eB[j];
                    P[i][j] = p;
                    rs += p;
                }
                tl[i] = rs;
            }
        } else {
            float rowB[4];
#pragma unroll
            for (int i = 0; i < 4; i++) {
                float rb = -INFINITY;
#pragma unroll
                for (int j = 0; j < 4; j++)
                    if (4 * tx + j <= 4 * ty + i) rb = fmaxf(rb, Bc[j]);
                rowB[i] = rb;
            }
#pragma unroll
            for (int i = 0; i < 4; i++) {
#pragma unroll
                for (int off = 1; off < 16; off <<= 1)
                    rowB[i] = fmaxf(rowB[i], __shfl_xor_sync(0xffffffffu, rowB[i], off, 16));
            }
#pragma unroll
            for (int i = 0; i < 4; i++) {
                const float mn = fmaxf(m[i], cumq[i] + rowB[i]);
                fs[i] = __expf(m[i] - mn);
                m[i] = mn;
                const float base = cumq[i] - mn;
                float rs = 0.f;
#pragma unroll
                for (int j = 0; j < 4; j++) {
                    const bool ok = (4 * tx + j <= 4 * ty + i);
                    const float p = ok ? acc[i][j] * (scale * __expf(base + Bc[j])) : 0.f;
                    P[i][j] = p;
                    rs += p;
                }
                tl[i] = rs;
            }
        }

#pragma unroll
        for (int i = 0; i < 4; i++) {
#pragma unroll
            for (int off = 1; off < 16; off <<= 1)
                tl[i] += __shfl_xor_sync(0xffffffffu, tl[i], off, 16);
            l[i] = l[i] * fs[i] + tl[i];
            const ull fsd = dup2f(fs[i]);
#pragma unroll
            for (int d = 0; d < 4; d++) o2[i][d] = fmul2(o2[i][d], fsd);
        }

        // stage P to smem: Ps[key][row]
#pragma unroll
        for (int j = 0; j < 4; j++) {
            float4 pv = make_float4(P[0][j], P[1][j], P[2][j], P[3][j]);
            *(float4*)(Ps + (c0 + j) * 68 + ty * 4) = pv;
        }

        cp_wait0();        // own V(kt) copies done
        __syncthreads();   // Ps + V(kt) visible; QK done by all (K buffer free)

        if (kt < qi)
            prefetch_swz(kg0 + (size_t)(t0 + BN) * EDIM, Ks, tid);  // {K(kt+1)}

        // ---- P @ V (packed f32x2), dims 4tx..+3 and 64+4tx..+3 ----
#pragma unroll 8
        for (int tt = 0; tt < 64; tt++) {
            const float4 p4 = *(const float4*)(Ps + tt * 68 + ty * 4);
            const ulonglong2 va = *(const ulonglong2*)(Vs + tt * 128 + tx * 4);
            const ulonglong2 vb = *(const ulonglong2*)(Vs + tt * 128 + 64 + tx * 4);
            const float pa[4] = {p4.x, p4.y, p4.z, p4.w};
#pragma unroll
            for (int i = 0; i < 4; i++) {
                const ull pd = dup2f(pa[i]);
                o2[i][0] = ffma2(pd, va.x, o2[i][0]);
                o2[i][1] = ffma2(pd, va.y, o2[i][1]);
                o2[i][2] = ffma2(pd, vb.x, o2[i][2]);
                o2[i][3] = ffma2(pd, vb.y, o2[i][3]);
            }
        }

        cp_wait0();        // own K(kt+1) copies done
        __syncthreads();   // K(kt+1) visible; PV done by all (V buffer free)

        if (kt < qi)
            prefetch_V(vg0 + (size_t)(t0 + BN) * EDIM, Vs, tid);    // {V(kt+1)}
    }

    // epilogue
#pragma unroll
    for (int i = 0; i < 4; i++) {
        const float norm = fmaxf(fabsf(l[i]), __expf(-m[i])) + 1e-6f;
        const ull iv = dup2f(1.f / norm);
        float* dst = g_h + (size_t)srow[i] * EDIM + h * DH;
        ulonglong2 ra, rb;
        ra.x = fmul2(o2[i][0], iv); ra.y = fmul2(o2[i][1], iv);
        rb.x = fmul2(o2[i][2], iv); rb.y = fmul2(o2[i][3], iv);
        *(ulonglong2*)(dst + tx * 4)      = ra;
        *(ulonglong2*)(dst + 64 + tx * 4) = rb;
    }
}

// ---------------------------------------------------------------------------
// Kernel 4: residual layer norm.
// ---------------------------------------------------------------------------
__global__ void ln_kernel(const float* __restrict__ lnw, float* __restrict__ out) {
    const int s = blockIdx.x;
    const int tid = threadIdx.x;
    const int lane = tid & 31, warp = tid >> 5;

    const float4 x = *(const float4*)(g_h + s * EDIM + tid * 4);

    __shared__ float wsum[8];
    __shared__ float stat[2];

    float lsum = x.x + x.y + x.z + x.w;
#pragma unroll
    for (int off = 16; off > 0; off >>= 1)
        lsum += __shfl_xor_sync(0xffffffffu, lsum, off);
    if (lane == 0) wsum[warp] = lsum;
    __syncthreads();
    if (tid == 0) {
        float t = 0.f;
#pragma unroll
        for (int w = 0; w < 8; w++) t += wsum[w];
        stat[0] = t * (1.f / 1024.f);
    }
    __syncthreads();
    const float mean = stat[0];

    const float d0 = x.x - mean, d1 = x.y - mean, d2 = x.z - mean, d3 = x.w - mean;
    float lsq = d0 * d0 + d1 * d1 + d2 * d2 + d3 * d3;
#pragma unroll
    for (int off = 16; off > 0; off >>= 1)
        lsq += __shfl_xor_sync(0xffffffffu, lsq, off);
    if (lane == 0) wsum[warp] = lsq;
    __syncthreads();
    if (tid == 0) {
        float t = 0.f;
#pragma unroll
        for (int w = 0; w < 8; w++) t += wsum[w];
        stat[1] = rsqrtf(t * (1.f / 1024.f) + 1e-5f);
    }
    __syncthreads();
    const float rstd = stat[1];

    const float4 w4 = *(const float4*)(lnw + tid * 4);
    float4 r;
    r.x = d0 * rstd * (1.f + w4.x);
    r.y = d1 * rstd * (1.f + w4.y);
    r.z = d2 * rstd * (1.f + w4.z);
    r.w = d3 * rstd * (1.f + w4.w);
    *(float4*)(out + s * EDIM + tid * 4) = r;
}

// ---------------------------------------------------------------------------
extern "C" void kernel_launch(void* const* d_in, const int* in_sizes, int n_in,
                              void* d_out, int out_size) {
    const float* q   = (const float*)d_in[0];
    const float* k   = (const float*)d_in[1];
    const float* v   = (const float*)d_in[2];
    const float* Wi  = (const float*)d_in[3];
    const float* bi  = (const float*)d_in[4];
    const float* Wf  = (const float*)d_in[5];
    const float* bf  = (const float*)d_in[6];
    const float* lnw = (const float*)d_in[7];
    float* out = (float*)d_out;

    gates_kernel<<<S_LEN / 4, 256>>>(q, k, v, Wi, bi, Wf, bf);
    scan_kernel<<<NH, 1024>>>();

    cudaFuncSetAttribute(mlstm_main_kernel,
                         cudaFuncAttributeMaxDynamicSharedMemorySize, SMEM_BYTES);
    mlstm_main_kernel<<<32 * NH, 256, SMEM_BYTES>>>(q, k, v);

    ln_kernel<<<S_LEN, 256>>>(lnw, out);
}

// round 11
// speedup vs baseline: 1.3432x; 1.3432x over previous
#include <cuda_runtime.h>
#include <math.h>
#include <stdint.h>

// Problem constants
#define S_LEN 2048
#define EDIM  1024
#define NH    8
#define DH    128
#define BM    64
#define BN    64

typedef unsigned long long ull;

// ---- packed f32x2 helpers (Blackwell FFMA2 — PTX-only path) ----
__device__ __forceinline__ ull ffma2(ull a, ull b, ull c) {
    ull d;
    asm("fma.rn.f32x2 %0, %1, %2, %3;" : "=l"(d) : "l"(a), "l"(b), "l"(c));
    return d;
}
__device__ __forceinline__ ull fmul2(ull a, ull b) {
    ull d;
    asm("mul.rn.f32x2 %0, %1, %2;" : "=l"(d) : "l"(a), "l"(b));
    return d;
}
__device__ __forceinline__ ull dup2f(float x) {
    ull d;
    asm("mov.b64 %0, {%1, %1};" : "=l"(d) : "f"(x));
    return d;
}
__device__ __forceinline__ void unpk2(ull v, float& lo, float& hi) {
    asm("mov.b64 {%0, %1}, %2;" : "=f"(lo), "=f"(hi) : "l"(v));
}
__device__ __forceinline__ void cp16(uint32_t dst, const float* src) {
    asm volatile("cp.async.cg.shared.global [%0], [%1], 16;" :: "r"(dst), "l"(src));
}
__device__ __forceinline__ void cp_commit() {
    asm volatile("cp.async.commit_group;");
}
__device__ __forceinline__ void cp_wait0() {
    asm volatile("cp.async.wait_group 0;");
}

// Scratch (device globals: no allocations allowed)
__device__ float g_ig   [NH * S_LEN];
__device__ float g_logf [NH * S_LEN];
__device__ float g_cumS [NH * S_LEN];   // inclusive scan of log_f
__device__ float g_B    [NH * S_LEN];   // B[t] = ig[t] - cum[t]
__device__ float g_pm   [NH * S_LEN];   // prefix max of B (inclusive)
__device__ float g_tileb[NH * 32];      // per-64-tile max of B
__device__ float g_h    [S_LEN * EDIM];

// ---------------------------------------------------------------------------
// Kernel 1: gate projections.
// ---------------------------------------------------------------------------
__global__ void gates_kernel(const float* __restrict__ q,
                             const float* __restrict__ k,
                             const float* __restrict__ v,
                             const float* __restrict__ Wi,
                             const float* __restrict__ bi,
                             const float* __restrict__ Wf,
                             const float* __restrict__ bf) {
    const int b = blockIdx.x;
    const int tid = threadIdx.x;

    float acc[64];
#pragma unroll
    for (int i = 0; i < 64; i++) acc[i] = 0.f;

#pragma unroll 1
    for (int it = 0; it < 12; it++) {
        const int j = it * 256 + tid;
        float wi[8], wf[8];
#pragma unroll
        for (int h = 0; h < 8; h++) {
            wi[h] = Wi[h * 3072 + j];
            wf[h] = Wf[h * 3072 + j];
        }
#pragma unroll
        for (int r = 0; r < 4; r++) {
            const int s = b * 4 + r;
            float x;
            if (j < 1024)       x = q[s * 1024 + j];
            else if (j < 2048)  x = k[s * 1024 + (j - 1024)];
            else                x = v[s * 1024 + (j - 2048)];
#pragma unroll
            for (int h = 0; h < 8; h++) {
                acc[r * 16 + h]     = fmaf(x, wi[h], acc[r * 16 + h]);
                acc[r * 16 + 8 + h] = fmaf(x, wf[h], acc[r * 16 + 8 + h]);
            }
        }
    }

#pragma unroll
    for (int i = 0; i < 64; i++) {
#pragma unroll
        for (int off = 16; off > 0; off >>= 1)
            acc[i] += __shfl_xor_sync(0xffffffffu, acc[i], off);
    }
    __shared__ float red[8][64];
    const int warp = tid >> 5, lane = tid & 31;
    if (lane == 0) {
#pragma unroll
        for (int i = 0; i < 64; i++) red[warp][i] = acc[i];
    }
    __syncthreads();
    if (tid < 64) {
        float vsum = 0.f;
#pragma unroll
        for (int w = 0; w < 8; w++) vsum += red[w][tid];
        const int r = tid >> 4;
        const int o = tid & 15;
        const int h = o & 7;
        const int s = b * 4 + r;
        if (o < 8) {
            g_ig[h * S_LEN + s] = vsum + bi[h];
        } else {
            const float fg = vsum + bf[h];
            g_logf[h * S_LEN + s] = fminf(fg, 0.f) - log1pf(expf(-fabsf(fg)));
        }
    }
}

// ---------------------------------------------------------------------------
// Kernel 2: per-head scan: cum (double), B, prefix-max(B), per-tile max(B).
// grid 8, 1024 threads (2 elems/thread; warp w == key-tile w).
// ---------------------------------------------------------------------------
__global__ void scan_kernel() {
    const int h = blockIdx.x;
    const int tid = threadIdx.x;
    const int lane = tid & 31, warp = tid >> 5;

    const double x0 = (double)g_logf[h * S_LEN + 2 * tid];
    const double x1 = (double)g_logf[h * S_LEN + 2 * tid + 1];
    const double s = x0 + x1;

    double inc = s;
#pragma unroll
    for (int off = 1; off < 32; off <<= 1) {
        double u = __shfl_up_sync(0xffffffffu, inc, off);
        if (lane >= off) inc += u;
    }
    __shared__ double wsum[32];
    if (lane == 31) wsum[warp] = inc;
    __syncthreads();
    if (warp == 0) {
        double w = wsum[lane];
#pragma unroll
        for (int off = 1; off < 32; off <<= 1) {
            double u = __shfl_up_sync(0xffffffffu, w, off);
            if (lane >= off) w += u;
        }
        wsum[lane] = w;
    }
    __syncthreads();
    const double base = (warp > 0) ? wsum[warp - 1] : 0.0;
    const double incl = base + inc;
    const double excl = incl - s;

    const float c0 = (float)(excl + x0);
    const float c1 = (float)incl;
    g_cumS[h * S_LEN + 2 * tid]     = c0;
    g_cumS[h * S_LEN + 2 * tid + 1] = c1;

    // B[t] = ig[t] - cum[t]
    const float B0 = g_ig[h * S_LEN + 2 * tid]     - c0;
    const float B1 = g_ig[h * S_LEN + 2 * tid + 1] - c1;
    g_B[h * S_LEN + 2 * tid]     = B0;
    g_B[h * S_LEN + 2 * tid + 1] = B1;

    const float mx = fmaxf(B0, B1);

    // per-tile (= per-warp) max of B
    float tb = mx;
#pragma unroll
    for (int off = 16; off > 0; off >>= 1)
        tb = fmaxf(tb, __shfl_xor_sync(0xffffffffu, tb, off));
    if (lane == 0) g_tileb[h * 32 + warp] = tb;

    // prefix max of B (inclusive at each t)
    float im = mx;
#pragma unroll
    for (int off = 1; off < 32; off <<= 1) {
        float u = __shfl_up_sync(0xffffffffu, im, off);
        if (lane >= off) im = fmaxf(im, u);
    }
    __shared__ float wm[32];
    if (lane == 31) wm[warp] = im;
    __syncthreads();
    if (warp == 0) {
        float w = wm[lane];
#pragma unroll
        for (int off = 1; off < 32; off <<= 1) {
            float u = __shfl_up_sync(0xffffffffu, w, off);
            if (lane >= off) w = fmaxf(w, u);
        }
        wm[lane] = w;
    }
    __syncthreads();
    const float bmbase = (warp > 0) ? wm[warp - 1] : -INFINITY;
    const float wexcl = __shfl_up_sync(0xffffffffu, im, 1);
    const float exclm = fmaxf(bmbase, (lane > 0) ? wexcl : -INFINITY);
    const float pm0 = fmaxf(exclm, B0);
    const float pm1 = fmaxf(pm0, B1);
    g_pm[h * S_LEN + 2 * tid]     = pm0;
    g_pm[h * S_LEN + 2 * tid + 1] = pm1;
}

// ---------------------------------------------------------------------------
// Kernel 3: main flash-style mLSTM attention. Double-buffered K/V (round-3
// pipeline), precomputed row-max (no online rescale, no in-loop shfls),
// 8x4 warp tiling. grid 256 = (32 qtiles x 8 heads), 256 threads.
// ---------------------------------------------------------------------------
#define QS_OFF 0
#define KS_OFF (64 * 128)                  // Q: 8192 floats (swizzled)
#define VS_OFF (KS_OFF + 2 * 64 * 128)     // K db: 16384
#define PS_OFF (VS_OFF + 2 * 64 * 128)     // V db: 16384
#define SMEM_FLOATS (PS_OFF + 64 * 68)     // P: 4352 -> 45312 fl = 181248 B
#define SMEM_BYTES (SMEM_FLOATS * 4)

// swizzled [64][128] tile: row r, 4-float chunk ch at (r*128 + ((ch^swz(r))<<2))
__device__ __forceinline__ void prefetch_swz(const float* __restrict__ g,
                                             float* sb, int tid) {
    uint32_t base = (uint32_t)__cvta_generic_to_shared(sb);
#pragma unroll
    for (int it = 0; it < 8; it++) {
        const int c = it * 256 + tid;
        const int row = c >> 5, ch = c & 31;
        const int swz = (row ^ (row >> 3)) & 7;
        cp16(base + (uint32_t)(row * 128 + ((ch ^ swz) << 2)) * 4u,
             g + row * EDIM + ch * 4);
    }
}
__device__ __forceinline__ void prefetch_V(const float* __restrict__ vg,
                                           float* Vsb, int tid) {
    uint32_t vbase = (uint32_t)__cvta_generic_to_shared(Vsb);
#pragma unroll
    for (int it = 0; it < 8; it++) {
        const int c = it * 256 + tid;
        const int key = c >> 5, ch = c & 31;
        cp16(vbase + (uint32_t)(key * 128 + (ch << 2)) * 4u,
             vg + key * EDIM + ch * 4);
    }
}

extern "C" __global__ void __launch_bounds__(256, 1)
mlstm_main_kernel(const float* __restrict__ q,
                  const float* __restrict__ k,
                  const float* __restrict__ v) {
    extern __shared__ float sm[];
    float* Qs  = sm + QS_OFF;    // [64][128] swizzled
    float* Ks0 = sm + KS_OFF;    // [64][128] swizzled, double-buffered
    float* Vs0 = sm + VS_OFF;    // [64][128] double-buffered
    float* Ps  = sm + PS_OFF;    // [64][68]  Ps[key][row]

    const int bx = blockIdx.x;
    const int qi = 31 - (bx >> 3);       // longest-work-first
    const int h  = bx & 7;
    const int tid = threadIdx.x;
    const int lane = tid & 31, warp = tid >> 5;
    const int wx = lane & 7, wy = lane >> 3;      // 8x4 within warp
    const int tx = wx + ((warp & 1) << 3);        // 0..15 (keys / dims)
    const int ty = wy + ((warp >> 1) << 2);       // 0..15 (query rows)

    const float scale = 0.08838834764831845f;  // 1/sqrt(128)
    const float* kg0 = k + h * DH;
    const float* vg0 = v + h * DH;
    const int qrow0 = qi * BM;

    // prefetch: {Q} then {K0,V0} — two commit groups, both awaited below
    prefetch_swz(q + (size_t)qrow0 * EDIM + h * DH, Qs, tid);
    cp_commit();
    prefetch_swz(kg0, Ks0, tid);
    prefetch_V(vg0, Vs0, tid);
    cp_commit();

    float pm[4];
    int srow[4];
#pragma unroll
    for (int i = 0; i < 4; i++) {
        srow[i] = qrow0 + ty * 4 + i;
        pm[i] = g_pm[h * S_LEN + srow[i]];
    }

    int kswz[4], qswz[4];
#pragma unroll
    for (int j = 0; j < 4; j++) {
        const int rk = 4 * tx + j;
        kswz[j] = (rk ^ (rk >> 3)) & 7;
        const int rq = 4 * ty + j;
        qswz[j] = (rq ^ (rq >> 3)) & 7;
    }

    float lpart[4];
    ull o2[4][4];
#pragma unroll
    for (int i = 0; i < 4; i++) {
        lpart[i] = 0.f;
#pragma unroll
        for (int d = 0; d < 4; d++) o2[i][d] = 0ull;
    }

    cp_wait0();
    __syncthreads();

    for (int kt = 0; kt <= qi; kt++) {
        const int t0 = kt * BN;
        float* Kb = Ks0 + (kt & 1) * (64 * 128);
        float* Vb = Vs0 + (kt & 1) * (64 * 128);

        // gate inputs for this thread's 4 keys
        const int c0 = tx * 4;
        const float4 Bv = *(const float4*)(g_B + h * S_LEN + t0 + c0);
        const float Bc[4] = {Bv.x, Bv.y, Bv.z, Bv.w};
        const float tb = g_tileb[h * 32 + kt];

        // ---- QK^T 64x64x128, dot along k, packed pairs ----
        ull acc2[4][4];
#pragma unroll
        for (int i = 0; i < 4; i++)
#pragma unroll
            for (int j = 0; j < 4; j++) acc2[i][j] = 0ull;

#pragma unroll 8
        for (int ch = 0; ch < 32; ch++) {
            ulonglong2 qv[4], kv[4];
#pragma unroll
            for (int i = 0; i < 4; i++)
                qv[i] = *(const ulonglong2*)(Qs + (4 * ty + i) * 128 + ((ch ^ qswz[i]) << 2));
#pragma unroll
            for (int j = 0; j < 4; j++)
                kv[j] = *(const ulonglong2*)(Kb + (4 * tx + j) * 128 + ((ch ^ kswz[j]) << 2));
#pragma unroll
            for (int i = 0; i < 4; i++)
#pragma unroll
                for (int j = 0; j < 4; j++) {
                    acc2[i][j] = ffma2(qv[i].x, kv[j].x, acc2[i][j]);
                    acc2[i][j] = ffma2(qv[i].y, kv[j].y, acc2[i][j]);
                }
        }
        float acc[4][4];
#pragma unroll
        for (int i = 0; i < 4; i++)
#pragma unroll
            for (int j = 0; j < 4; j++) {
                float lo, hi; unpk2(acc2[i][j], lo, hi);
                acc[i][j] = lo + hi;
            }

        // ---- gate math: no reductions, no rescaling ----
        float P[4][4];
        if (kt < qi) {
            float eB[4];
#pragma unroll
            for (int j = 0; j < 4; j++) eB[j] = __expf(Bc[j] - tb);
#pragma unroll
            for (int i = 0; i < 4; i++) {
                const float eA = scale * __expf(tb - pm[i]);
                float rs = 0.f;
#pragma unroll
                for (int j = 0; j < 4; j++) {
                    const float p = acc[i][j] * (eA * eB[j]);
                    P[i][j] = p;
                    rs += p;
                }
                lpart[i] += rs;
            }
        } else {
            // diagonal tile: masked, per-element exp
#pragma unroll
            for (int i = 0; i < 4; i++) {
                float rs = 0.f;
#pragma unroll
                for (int j = 0; j < 4; j++) {
                    const bool ok = (4 * tx + j <= 4 * ty + i);
                    const float p = ok ? acc[i][j] * (scale * __expf(Bc[j] - pm[i])) : 0.f;
                    P[i][j] = p;
                    rs += p;
                }
                lpart[i] += rs;
            }
        }

        // stage P to smem: Ps[key][row]
#pragma unroll
        for (int j = 0; j < 4; j++) {
            float4 pv = make_float4(P[0][j], P[1][j], P[2][j], P[3][j]);
            *(float4*)(Ps + (c0 + j) * 68 + ty * 4) = pv;
        }
        __syncthreads();   // Ps visible; QK done by all

        if (kt < qi) {
            prefetch_swz(kg0 + (size_t)(t0 + BN) * EDIM,
                         Ks0 + ((kt + 1) & 1) * (64 * 128), tid);
            prefetch_V(vg0 + (size_t)(t0 + BN) * EDIM,
                       Vs0 + ((kt + 1) & 1) * (64 * 128), tid);
            cp_commit();
        }

        // ---- P @ V (packed f32x2), dims 4tx..+3 and 64+4tx..+3 ----
#pragma unroll 8
        for (int tt = 0; tt < 64; tt++) {
            const float4 p4 = *(const float4*)(Ps + tt * 68 + ty * 4);
            const ulonglong2 va = *(const ulonglong2*)(Vb + tt * 128 + tx * 4);
            const ulonglong2 vb = *(const ulonglong2*)(Vb + tt * 128 + 64 + tx * 4);
            const float pa[4] = {p4.x, p4.y, p4.z, p4.w};
#pragma unroll
            for (int i = 0; i < 4; i++) {
                const ull pd = dup2f(pa[i]);
                o2[i][0] = ffma2(pd, va.x, o2[i][0]);
                o2[i][1] = ffma2(pd, va.y, o2[i][1]);
                o2[i][2] = ffma2(pd, vb.x, o2[i][2]);
                o2[i][3] = ffma2(pd, vb.y, o2[i][3]);
            }
        }

        if (kt < qi) cp_wait0();
        __syncthreads();   // next tile ready; PV done (buffers rotatable)
    }

    // ---- epilogue: reduce lpart across the 16 tx groups, then normalize ----
    // step 1: reduce over wx (8 lanes share wy)
#pragma unroll
    for (int i = 0; i < 4; i++) {
#pragma unroll
        for (int off = 1; off < 8; off <<= 1)
            lpart[i] += __shfl_xor_sync(0xffffffffu, lpart[i], off);
    }
    // step 2: combine the two warp-parities via smem (reuse Ps)
    float* Lred = Ps;   // [64][2]
    if (wx == 0) {
#pragma unroll
        for (int i = 0; i < 4; i++)
            Lred[(4 * ty + i) * 2 + (warp & 1)] = lpart[i];
    }
    __syncthreads();

#pragma unroll
    for (int i = 0; i < 4; i++) {
        const float l = Lred[(4 * ty + i) * 2] + Lred[(4 * ty + i) * 2 + 1];
        const float cumq = g_cumS[h * S_LEN + srow[i]];
        const float norm = fmaxf(fabsf(l), __expf(-(cumq + pm[i]))) + 1e-6f;
        const ull iv = dup2f(1.f / norm);
        float* dst = g_h + (size_t)srow[i] * EDIM + h * DH;
        ulonglong2 ra, rb;
        ra.x = fmul2(o2[i][0], iv); ra.y = fmul2(o2[i][1], iv);
        rb.x = fmul2(o2[i][2], iv); rb.y = fmul2(o2[i][3], iv);
        *(ulonglong2*)(dst + tx * 4)      = ra;
        *(ulonglong2*)(dst + 64 + tx * 4) = rb;
    }
}

// ---------------------------------------------------------------------------
// Kernel 4: residual layer norm.
// ---------------------------------------------------------------------------
__global__ void ln_kernel(const float* __restrict__ lnw, float* __restrict__ out) {
    const int s = blockIdx.x;
    const int tid = threadIdx.x;
    const int lane = tid & 31, warp = tid >> 5;

    const float4 x = *(const float4*)(g_h + s * EDIM + tid * 4);

    __shared__ float wsum[8];
    __shared__ float stat[2];

    float lsum = x.x + x.y + x.z + x.w;
#pragma unroll
    for (int off = 16; off > 0; off >>= 1)
        lsum += __shfl_xor_sync(0xffffffffu, lsum, off);
    if (lane == 0) wsum[warp] = lsum;
    __syncthreads();
    if (tid == 0) {
        float t = 0.f;
#pragma unroll
        for (int w = 0; w < 8; w++) t += wsum[w];
        stat[0] = t * (1.f / 1024.f);
    }
    __syncthreads();
    const float mean = stat[0];

    const float d0 = x.x - mean, d1 = x.y - mean, d2 = x.z - mean, d3 = x.w - mean;
    float lsq = d0 * d0 + d1 * d1 + d2 * d2 + d3 * d3;
#pragma unroll
    for (int off = 16; off > 0; off >>= 1)
        lsq += __shfl_xor_sync(0xffffffffu, lsq, off);
    if (lane == 0) wsum[warp] = lsq;
    __syncthreads();
    if (tid == 0) {
        float t = 0.f;
#pragma unroll
        for (int w = 0; w < 8; w++) t += wsum[w];
        stat[1] = rsqrtf(t * (1.f / 1024.f) + 1e-5f);
    }
    __syncthreads();
    const float rstd = stat[1];

    const float4 w4 = *(const float4*)(lnw + tid * 4);
    float4 r;
    r.x = d0 * rstd * (1.f + w4.x);
    r.y = d1 * rstd * (1.f + w4.y);
    r.z = d2 * rstd * (1.f + w4.z);
    r.w = d3 * rstd * (1.f + w4.w);
    *(float4*)(out + s * EDIM + tid * 4) = r;
}

// ---------------------------------------------------------------------------
extern "C" void kernel_launch(void* const* d_in, const int* in_sizes, int n_in,
                              void* d_out, int out_size) {
    const float* q   = (const float*)d_in[0];
    const float* k   = (const float*)d_in[1];
    const float* v   = (const float*)d_in[2];
    const float* Wi  = (const float*)d_in[3];
    const float* bi  = (const float*)d_in[4];
    const float* Wf  = (const float*)d_in[5];
    const float* bf  = (const float*)d_in[6];
    const float* lnw = (const float*)d_in[7];
    float* out = (float*)d_out;

    gates_kernel<<<S_LEN / 4, 256>>>(q, k, v, Wi, bi, Wf, bf);
    scan_kernel<<<NH, 1024>>>();

    cudaFuncSetAttribute(mlstm_main_kernel,
                         cudaFuncAttributeMaxDynamicSharedMemorySize, SMEM_BYTES);
    mlstm_main_kernel<<<32 * NH, 256, SMEM_BYTES>>>(q, k, v);

    ln_kernel<<<S_LEN, 256>>>(lnw, out);
}